// round 8
// baseline (speedup 1.0000x reference)
#include <cuda_runtime.h>
#include <math.h>

#define BATCH 2
#define DIM   48
#define HEADS 8
#define CPH   6
#define HH    384
#define WW    384
#define NPIX  (HH*WW)

// ---------------- scratch ----------------
__device__ float g_pwkv[BATCH*2*DIM*NPIX];    // only v-half (ch 48..95) used now
__device__ float g_v   [BATCH*DIM*NPIX];
__device__ float g_acc [BATCH*HEADS*48];      // 36 Gram + 6 |q|^2 + 6 |k|^2
__device__ float g_meff[BATCH*DIM*DIM];

// ---------------- packed f32x2 ----------------
__device__ __forceinline__ unsigned long long pk2(float lo, float hi){
    unsigned long long r;
    asm("mov.b64 %0, {%1,%2};" : "=l"(r) : "f"(lo), "f"(hi));
    return r;
}
__device__ __forceinline__ void fma2(unsigned long long &d,
                                     unsigned long long a,
                                     unsigned long long b){
    asm("fma.rn.f32x2 %0, %1, %2, %3;" : "=l"(d) : "l"(a), "l"(b), "l"(d));
}
__device__ __forceinline__ float2 unpk(unsigned long long v){
    float lo, hi;
    asm("mov.b64 {%0,%1}, %2;" : "=f"(lo), "=f"(hi) : "l"(v));
    return make_float2(lo, hi);
}

__device__ __forceinline__ void cpa16(unsigned int dst, const float* src){
    asm volatile("cp.async.cg.shared.global [%0], [%1], 16;" :: "r"(dst), "l"(src) : "memory");
}
__device__ __forceinline__ void cpa_commit(){
    asm volatile("cp.async.commit_group;" ::: "memory");
}
template<int N>
__device__ __forceinline__ void cpa_wait(){
    asm volatile("cp.async.wait_group %0;" :: "n"(N) : "memory");
}

// Upfront-window depthwise conv (global-memory version, for v branch)
template<int R>
__device__ __forceinline__ void winconv(const float* __restrict__ chan, int x,
                                        bool xm, bool xp, int ytop, bool fast,
                                        const float* __restrict__ wr, float* out){
    float v[R][3];
    if (fast){
        const float* rp = chan + (size_t)ytop*WW + x;
        #pragma unroll
        for (int r = 0; r < R; r++){
            v[r][0] = __ldg(rp + r*WW - 1);
            v[r][1] = __ldg(rp + r*WW    );
            v[r][2] = __ldg(rp + r*WW + 1);
        }
    } else {
        int xl = max(x-1, 0), xr = min(x+1, WW-1);
        #pragma unroll
        for (int r = 0; r < R; r++){
            int yy = ytop + r; bool yok = (yy >= 0 && yy < HH);
            const float* rp = chan + (size_t)(yok ? yy : 0)*WW;
            v[r][0] = (yok && xm) ? __ldg(rp + xl) : 0.f;
            v[r][1] =  yok        ? __ldg(rp + x ) : 0.f;
            v[r][2] = (yok && xp) ? __ldg(rp + xr) : 0.f;
        }
    }
    #pragma unroll
    for (int i = 0; i < R-2; i++){
        out[i] = wr[0]*v[i  ][0] + wr[1]*v[i  ][1] + wr[2]*v[i  ][2]
               + wr[3]*v[i+1][0] + wr[4]*v[i+1][1] + wr[5]*v[i+1][2]
               + wr[6]*v[i+2][0] + wr[7]*v[i+2][1] + wr[8]*v[i+2][2];
    }
}

// ---------------- kernels ----------------
__global__ void zero_acc_kernel(){
    int t = blockIdx.x*blockDim.x + threadIdx.x;
    if (t < BATCH*HEADS*48) g_acc[t] = 0.f;
}

// 1x1 conv as GEMM with cp.async double-buffered input staging (v-half & out-GEMM).
__global__ __launch_bounds__(256, 2) void pw_cp_kernel(const float* __restrict__ in,
                                                       const float* __restrict__ W,
                                                       float* __restrict__ out,
                                                       int inBC, int outBC,
                                                       int zbase, int wStride){
    __shared__ unsigned long long ws[DIM*DIM];
    __shared__ float xs[2][8*256];

    const int b  = blockIdx.y;
    const int zh = blockIdx.z + zbase;
    const float* Wb = W + b*wStride + zh*DIM*DIM;
    for (int t = threadIdx.x; t < DIM*DIM; t += 256){
        float w = Wb[t];
        ws[t] = pk2(w, w);
    }

    const int tid  = threadIdx.x;
    const int base = blockIdx.x*256;
    const float* inp = in + (size_t)b*inBC*NPIX + base;
    const unsigned int xsu = (unsigned int)__cvta_generic_to_shared(&xs[0][0]);

    auto issue = [&](int c, int buf){
        #pragma unroll
        for (int r = 0; r < 2; r++){
            int e   = tid + r*256;
            int icl = e >> 6;
            int q   = e & 63;
            cpa16(xsu + (unsigned int)((buf*2048 + icl*256 + q*4)*4),
                  inp + (size_t)(c*8 + icl)*NPIX + q*4);
        }
        cpa_commit();
    };

    issue(0, 0);

    const int pxq = tid & 31;
    const int ocg = tid >> 5;

    unsigned long long acc[CPH][4];
    #pragma unroll
    for (int j = 0; j < CPH; j++){
        acc[j][0]=0ull; acc[j][1]=0ull; acc[j][2]=0ull; acc[j][3]=0ull;
    }

    #pragma unroll
    for (int c = 0; c < 6; c++){
        if (c < 5) issue(c+1, (c+1)&1);
        if (c < 5) cpa_wait<1>(); else cpa_wait<0>();
        __syncthreads();

        const float* xb = &xs[c&1][0];
        #pragma unroll
        for (int icl = 0; icl < 8; icl++){
            const float4* xp = reinterpret_cast<const float4*>(xb + icl*256 + pxq*8);
            float4 xa = xp[0];
            float4 xc = xp[1];
            unsigned long long a01 = pk2(xa.x, xa.y), a23 = pk2(xa.z, xa.w);
            unsigned long long b01 = pk2(xc.x, xc.y), b23 = pk2(xc.z, xc.w);
            #pragma unroll
            for (int j = 0; j < CPH; j++){
                unsigned long long w = ws[(ocg*CPH + j)*DIM + c*8 + icl];
                fma2(acc[j][0], a01, w);
                fma2(acc[j][1], a23, w);
                fma2(acc[j][2], b01, w);
                fma2(acc[j][3], b23, w);
            }
        }
        __syncthreads();
    }

    float* op = out + (size_t)b*outBC*NPIX + base + pxq*8;
    #pragma unroll
    for (int j = 0; j < CPH; j++){
        float* o = op + (size_t)(zh*DIM + ocg*CPH + j)*NPIX;
        float2 l0 = unpk(acc[j][0]), h0 = unpk(acc[j][1]);
        float2 l1 = unpk(acc[j][2]), h1 = unpk(acc[j][3]);
        *reinterpret_cast<float4*>(o)     = make_float4(l0.x, l0.y, h0.x, h0.y);
        *reinterpret_cast<float4*>(o + 4) = make_float4(l1.x, l1.y, h1.x, h1.y);
    }
}

// ============ fused pw + dw + Gram megakernel for q,k ============
// Block = (b, 32x8 tile). Halo staged as 48ic x 10row x 40col (16B-aligned).
// Warp w owns head w (oc w*6..w*6+5 of both q and k).
__global__ __launch_bounds__(256, 1) void mega_qk_kernel(
    const float* __restrict__ evs,
    const float* __restrict__ img,
    const float* __restrict__ Wq1,
    const float* __restrict__ Wkv1,
    const float* __restrict__ Wq2,
    const float* __restrict__ Wkv2)
{
    extern __shared__ float sm[];
    float* stg   = sm;                      // 2 x 3200 floats
    float* pwbuf = sm + 6400;               // 48 x 400
    float* ktile = sm + 25600;              // 48 x 256
    unsigned long long* wpw = reinterpret_cast<unsigned long long*>(sm + 37888); // 48x48
    float* wdk = sm + 42496;                // 48*9
    float* wdq = sm + 42928;                // 48*9

    const int tid = threadIdx.x, lane = tid & 31, wg = tid >> 5;
    const int b  = blockIdx.z;
    const int x0 = blockIdx.x*32, y0 = blockIdx.y*8;
    const unsigned int stg_u = (unsigned int)__cvta_generic_to_shared(stg);

    for (int t = tid; t < DIM*9; t += 256){
        wdk[t] = Wkv2[(t/9)*27 + 9 + t%9];
        wdq[t] = Wq2 [(t/9)*27 + 9 + t%9];
    }

    const float* imgb = img + (size_t)b*DIM*NPIX;
    const float* evsb = evs + (size_t)b*DIM*NPIX;

    auto stage = [&](const float* src, int c, int buf){
        for (int e = tid; e < 800; e += 256){
            int icl = e/100, rem = e%100, r = rem/10, q4 = rem%10;
            int gx = x0 - 4 + q4*4, gy = y0 - 1 + r;
            int off = buf*3200 + icl*400 + r*40 + q4*4;
            if (gy >= 0 && gy < HH && gx >= 0 && gx <= WW-4){
                cpa16(stg_u + (unsigned int)off*4,
                      src + (size_t)(c*8 + icl)*NPIX + (size_t)gy*WW + gx);
            } else {
                *reinterpret_cast<float4*>(stg + off) = make_float4(0.f,0.f,0.f,0.f);
            }
        }
        cpa_commit();
    };

    // pw GEMM over the 400-px halo for this warp's 6 oc; result -> pwbuf
    auto pw_phase = [&](const float* src, const float* W1){
        for (int t = tid; t < DIM*DIM; t += 256){
            float w = W1[t];
            wpw[t] = pk2(w, w);
        }
        unsigned long long acc[CPH][7];
        #pragma unroll
        for (int j = 0; j < CPH; j++)
            #pragma unroll
            for (int i = 0; i < 7; i++) acc[j][i] = 0ull;

        stage(src, 0, 0);
        #pragma unroll 1
        for (int c = 0; c < 6; c++){
            if (c < 5) stage(src, c+1, (c+1)&1);
            if (c < 5) cpa_wait<1>(); else cpa_wait<0>();
            __syncthreads();

            const float* xb = stg + (c&1)*3200;
            #pragma unroll
            for (int icl = 0; icl < 8; icl++){
                unsigned long long xv[7];
                #pragma unroll
                for (int i = 0; i < 7; i++){
                    int p = lane + i*32;
                    xv[i] = (p < 200)
                        ? *reinterpret_cast<const unsigned long long*>(xb + icl*400 + 2*p)
                        : 0ull;
                }
                #pragma unroll
                for (int j = 0; j < CPH; j++){
                    unsigned long long w = wpw[(wg*CPH + j)*DIM + c*8 + icl];
                    #pragma unroll
                    for (int i = 0; i < 7; i++) fma2(acc[j][i], xv[i], w);
                }
            }
            __syncthreads();
        }
        float* pb = pwbuf + wg*CPH*400;
        #pragma unroll
        for (int j = 0; j < CPH; j++)
            #pragma unroll
            for (int i = 0; i < 7; i++){
                int p = lane + i*32;
                if (p < 200)
                    *reinterpret_cast<unsigned long long*>(pb + j*400 + 2*p) = acc[j][i];
            }
    };

    // depthwise 3x3 from pwbuf plane; lane = output x column; 8 outputs
    auto dwconv = [&](const float* pb, const float* wr, float* o8){
        float c0[10], c1[10], c2[10];
        #pragma unroll
        for (int r = 0; r < 10; r++){
            c0[r] = pb[r*40 + lane + 3];
            c1[r] = pb[r*40 + lane + 4];
            c2[r] = pb[r*40 + lane + 5];
        }
        #pragma unroll
        for (int y = 0; y < 8; y++){
            o8[y] = wr[0]*c0[y]   + wr[1]*c1[y]   + wr[2]*c2[y]
                  + wr[3]*c0[y+1] + wr[4]*c1[y+1] + wr[5]*c2[y+1]
                  + wr[6]*c0[y+2] + wr[7]*c1[y+2] + wr[8]*c2[y+2];
        }
    };

    // ---- phase K: pw(img) -> dw -> ktile + kn ----
    pw_phase(imgb, Wkv1);
    float kn[CPH];
    #pragma unroll
    for (int j = 0; j < CPH; j++){
        int oc = wg*CPH + j;
        float o[8];
        dwconv(pwbuf + oc*400, wdk + oc*9, o);
        float s = 0.f;
        #pragma unroll
        for (int y = 0; y < 8; y++){
            ktile[oc*256 + y*32 + lane] = o[y];
            s += o[y]*o[y];
        }
        kn[j] = s;
    }

    // ---- phase Q: pw(evs) -> dw -> Gram vs ktile ----
    pw_phase(evsb, Wq1);

    float kt[CPH][8];
    #pragma unroll
    for (int d = 0; d < CPH; d++)
        #pragma unroll
        for (int y = 0; y < 8; y++)
            kt[d][y] = ktile[(wg*CPH + d)*256 + y*32 + lane];

    float G[36], qn[CPH];
    #pragma unroll
    for (int i = 0; i < 36; i++) G[i] = 0.f;
    #pragma unroll
    for (int j = 0; j < CPH; j++){
        int oc = wg*CPH + j;
        float qv[8];
        dwconv(pwbuf + oc*400, wdq + oc*9, qv);
        float s = 0.f;
        #pragma unroll
        for (int y = 0; y < 8; y++) s += qv[y]*qv[y];
        qn[j] = s;
        #pragma unroll
        for (int d = 0; d < CPH; d++){
            float g = 0.f;
            #pragma unroll
            for (int y = 0; y < 8; y++) g += qv[y]*kt[d][y];
            G[j*CPH + d] += g;
        }
    }

    // ---- reduce (per warp = per head) + global atomics ----
    float* accb = g_acc + (b*HEADS + wg)*48;
    #pragma unroll
    for (int j = 0; j < 36; j++){
        float v = G[j];
        #pragma unroll
        for (int o = 16; o; o >>= 1) v += __shfl_xor_sync(0xffffffffu, v, o);
        if (lane == 0) atomicAdd(&accb[j], v);
    }
    #pragma unroll
    for (int j = 0; j < CPH; j++){
        float v = qn[j];
        #pragma unroll
        for (int o = 16; o; o >>= 1) v += __shfl_xor_sync(0xffffffffu, v, o);
        if (lane == 0) atomicAdd(&accb[36 + j], v);
        float u = kn[j];
        #pragma unroll
        for (int o = 16; o; o >>= 1) u += __shfl_xor_sync(0xffffffffu, u, o);
        if (lane == 0) atomicAdd(&accb[42 + j], u);
    }
}

// softmax + fold Wout -> Meff[b] (48x48)
__global__ void attn_kernel(const float* __restrict__ Wout,
                            const float* __restrict__ temp){
    __shared__ float attn_s[BATCH*HEADS*36];
    int t = threadIdx.x;
    if (t < BATCH*HEADS*CPH){
        int b  = t/(HEADS*CPH);
        int h  = (t/CPH)%HEADS;
        int c6 = t%CPH;
        const float* a = g_acc + (b*HEADS + h)*48;
        float qnorm = fmaxf(sqrtf(a[36 + c6]), 1e-12f);
        float s[CPH];
        float mx = -1e30f;
        #pragma unroll
        for (int d6 = 0; d6 < CPH; d6++){
            float knorm = fmaxf(sqrtf(a[42 + d6]), 1e-12f);
            float v = a[c6*CPH + d6] / (qnorm*knorm) * temp[h];
            s[d6] = v; mx = fmaxf(mx, v);
        }
        float sum = 0.f;
        #pragma unroll
        for (int d6 = 0; d6 < CPH; d6++){ s[d6] = expf(s[d6]-mx); sum += s[d6]; }
        float inv = 1.f/sum;
        #pragma unroll
        for (int d6 = 0; d6 < CPH; d6++)
            attn_s[(b*HEADS + h)*36 + c6*CPH + d6] = s[d6]*inv;
    }
    __syncthreads();
    for (int e = t; e < BATCH*DIM*DIM; e += blockDim.x){
        int b = e/(DIM*DIM), rem = e%(DIM*DIM), o = rem/DIM, d = rem%DIM;
        int h = d/CPH, d6 = d%CPH;
        float s = 0.f;
        #pragma unroll
        for (int c6 = 0; c6 < CPH; c6++)
            s += Wout[o*DIM + h*CPH + c6] * attn_s[(b*HEADS + h)*36 + c6*CPH + d6];
        g_meff[e] = s;
    }
}

// depthwise 3x3 for v channels -> g_v
__global__ __launch_bounds__(256, 2) void v_conv_kernel(const float* __restrict__ Wkv2){
    __shared__ float wv[DIM*9];
    const int tid = threadIdx.x;
    for (int t = tid; t < DIM*9; t += 256)
        wv[t] = Wkv2[(DIM + t/9)*27 + 9 + (t%9)];
    __syncthreads();

    const int lane = tid & 31;
    const int w    = tid >> 5;
    const int b    = blockIdx.z;
    const int x0   = blockIdx.x*32;
    const int x    = x0 + lane;
    const int yb   = blockIdx.y*8;
    const bool xm = (x > 0), xp = (x < WW-1);
    const bool fast = (x0 > 0) && (x0 + 32 < WW) && (yb > 0) && (yb + 9 < HH);

    const float* vbase = g_pwkv + (size_t)b*2*DIM*NPIX + (size_t)DIM*NPIX;
    float* vo = g_v + (size_t)b*DIM*NPIX;
    #pragma unroll
    for (int c6 = 0; c6 < CPH; c6++){
        int c = w*CPH + c6;
        float o[8];
        winconv<10>(vbase + (size_t)c*NPIX, x, xm, xp, yb - 1, fast, &wv[c*9], o);
        #pragma unroll
        for (int i = 0; i < 8; i++)
            vo[(size_t)c*NPIX + (size_t)(yb + i)*WW + x] = o[i];
    }
}

// ---------------- launch ----------------
extern "C" void kernel_launch(void* const* d_in, const int* in_sizes, int n_in,
                              void* d_out, int out_size){
    const float* img  = (const float*)d_in[0];
    const float* evs  = (const float*)d_in[1];
    const float* Wq1  = (const float*)d_in[2];
    const float* Wq2  = (const float*)d_in[3];
    const float* Wkv1 = (const float*)d_in[4];
    const float* Wkv2 = (const float*)d_in[5];
    const float* Wout = (const float*)d_in[6];
    const float* temp = (const float*)d_in[7];
    float* out = (float*)d_out;

    float *pwkv, *vbuf, *meff;
    cudaGetSymbolAddress((void**)&pwkv, g_pwkv);
    cudaGetSymbolAddress((void**)&vbuf, g_v);
    cudaGetSymbolAddress((void**)&meff, g_meff);

    static cudaStream_t s2 = nullptr;
    static cudaEvent_t  evF = nullptr, evV = nullptr;
    if (s2 == nullptr){
        cudaStreamCreateWithFlags(&s2, cudaStreamNonBlocking);
        cudaEventCreateWithFlags(&evF, cudaEventDisableTiming);
        cudaEventCreateWithFlags(&evV, cudaEventDisableTiming);
    }

    const int smem_mega = 43360*4;   // 173,440 B
    cudaFuncSetAttribute(mega_qk_kernel, cudaFuncAttributeMaxDynamicSharedMemorySize, smem_mega);

    zero_acc_kernel<<<3, 256>>>();

    cudaEventRecord(evF, 0);
    cudaStreamWaitEvent(s2, evF, 0);

    // s2: v branch (pw v-half, then depthwise)
    dim3 gpw(NPIX/256, BATCH, 1);
    pw_cp_kernel<<<gpw, 256, 0, s2>>>(img, Wkv1, pwkv, DIM, 2*DIM, 1, 0);
    dim3 gvc(WW/32, HH/8, BATCH);
    v_conv_kernel<<<gvc, 256, 0, s2>>>(Wkv2);
    cudaEventRecord(evV, s2);

    // main: fused qk -> attn -> out GEMM
    dim3 gmega(WW/32, HH/8, BATCH);
    mega_qk_kernel<<<gmega, 256, smem_mega>>>(evs, img, Wq1, Wkv1, Wq2, Wkv2);

    attn_kernel<<<1, 256>>>(Wout, temp);

    cudaStreamWaitEvent(0, evV, 0);
    pw_cp_kernel<<<gpw, 256>>>(vbuf, meff, out, DIM, DIM, 0, DIM*DIM);
}

// round 9
// speedup vs baseline: 1.1494x; 1.1494x over previous
#include <cuda_runtime.h>
#include <math.h>

#define BATCH 2
#define DIM   48
#define HEADS 8
#define CPH   6
#define HH    384
#define WW    384
#define NPIX  (HH*WW)

// ---------------- scratch ----------------
__device__ float g_pwq [BATCH*DIM*NPIX];      // 56.6 MB
__device__ float g_pwkv[BATCH*2*DIM*NPIX];    // 113 MB (k: ch 0..47, v: ch 48..95)
__device__ float g_v   [BATCH*DIM*NPIX];      // 56.6 MB (dw-conv'd v)
__device__ float g_acc [BATCH*HEADS*48];      // 36 Gram + 6 |q|^2 + 6 |k|^2
__device__ float g_meff[BATCH*DIM*DIM];

// ---------------- packed f32x2 ----------------
__device__ __forceinline__ unsigned long long pk2(float lo, float hi){
    unsigned long long r;
    asm("mov.b64 %0, {%1,%2};" : "=l"(r) : "f"(lo), "f"(hi));
    return r;
}
__device__ __forceinline__ void fma2(unsigned long long &d,
                                     unsigned long long a,
                                     unsigned long long b){
    asm("fma.rn.f32x2 %0, %1, %2, %3;" : "=l"(d) : "l"(a), "l"(b), "l"(d));
}
__device__ __forceinline__ float2 unpk(unsigned long long v){
    float lo, hi;
    asm("mov.b64 {%0,%1}, %2;" : "=f"(lo), "=f"(hi) : "l"(v));
    return make_float2(lo, hi);
}

__device__ __forceinline__ void cpa16(unsigned int dst, const float* src){
    asm volatile("cp.async.cg.shared.global [%0], [%1], 16;" :: "r"(dst), "l"(src) : "memory");
}
__device__ __forceinline__ void cpa_commit(){
    asm volatile("cp.async.commit_group;" ::: "memory");
}
template<int N>
__device__ __forceinline__ void cpa_wait(){
    asm volatile("cp.async.wait_group %0;" :: "n"(N) : "memory");
}
__device__ __forceinline__ void cpa_wait_n(int n){
    switch(n){
        case 0: cpa_wait<0>(); break;
        case 1: cpa_wait<1>(); break;
        case 2: cpa_wait<2>(); break;
        case 3: cpa_wait<3>(); break;
        case 4: cpa_wait<4>(); break;
        default: cpa_wait<5>(); break;
    }
}

// Upfront-window depthwise conv (global-memory version)
template<int R>
__device__ __forceinline__ void winconv(const float* __restrict__ chan, int x,
                                        bool xm, bool xp, int ytop, bool fast,
                                        const float* __restrict__ wr, float* out){
    float v[R][3];
    if (fast){
        const float* rp = chan + (size_t)ytop*WW + x;
        #pragma unroll
        for (int r = 0; r < R; r++){
            v[r][0] = __ldg(rp + r*WW - 1);
            v[r][1] = __ldg(rp + r*WW    );
            v[r][2] = __ldg(rp + r*WW + 1);
        }
    } else {
        int xl = max(x-1, 0), xr = min(x+1, WW-1);
        #pragma unroll
        for (int r = 0; r < R; r++){
            int yy = ytop + r; bool yok = (yy >= 0 && yy < HH);
            const float* rp = chan + (size_t)(yok ? yy : 0)*WW;
            v[r][0] = (yok && xm) ? __ldg(rp + xl) : 0.f;
            v[r][1] =  yok        ? __ldg(rp + x ) : 0.f;
            v[r][2] = (yok && xp) ? __ldg(rp + xr) : 0.f;
        }
    }
    #pragma unroll
    for (int i = 0; i < R-2; i++){
        out[i] = wr[0]*v[i  ][0] + wr[1]*v[i  ][1] + wr[2]*v[i  ][2]
               + wr[3]*v[i+1][0] + wr[4]*v[i+1][1] + wr[5]*v[i+1][2]
               + wr[6]*v[i+2][0] + wr[7]*v[i+2][1] + wr[8]*v[i+2][2];
    }
}

// ---------------- kernels ----------------
__global__ void zero_acc_kernel(){
    int t = blockIdx.x*blockDim.x + threadIdx.x;
    if (t < BATCH*HEADS*48) g_acc[t] = 0.f;
}

// 1x1 conv as GEMM, DEEP cp.async prefetch: all 6 ic-chunks staged upfront.
// Block: 256 threads, 256 px, 48 oc (oc-half = blockIdx.z + zbase).
__global__ __launch_bounds__(256, 2) void pw_cp_kernel(const float* __restrict__ in,
                                                       const float* __restrict__ W,
                                                       float* __restrict__ out,
                                                       int inBC, int outBC,
                                                       int zbase, int wStride){
    __shared__ unsigned long long ws[DIM*DIM];   // 18 KB
    __shared__ float xs[6][8*256];               // 48 KB

    const int b  = blockIdx.y;
    const int zh = blockIdx.z + zbase;
    const float* Wb = W + b*wStride + zh*DIM*DIM;

    const int tid  = threadIdx.x;
    const int base = blockIdx.x*256;
    const float* inp = in + (size_t)b*inBC*NPIX + base;
    const unsigned int xsu = (unsigned int)__cvta_generic_to_shared(&xs[0][0]);

    // stage ALL 6 chunks as 6 groups (deep prefetch)
    #pragma unroll
    for (int c = 0; c < 6; c++){
        #pragma unroll
        for (int r = 0; r < 2; r++){
            int e   = tid + r*256;
            int icl = e >> 6;
            int q   = e & 63;
            cpa16(xsu + (unsigned int)((c*2048 + icl*256 + q*4)*4),
                  inp + (size_t)(c*8 + icl)*NPIX + q*4);
        }
        cpa_commit();
    }

    // weights while copies fly
    for (int t = tid; t < DIM*DIM; t += 256){
        float w = Wb[t];
        ws[t] = pk2(w, w);
    }

    const int pxq = tid & 31;
    const int ocg = tid >> 5;

    unsigned long long acc[CPH][4];
    #pragma unroll
    for (int j = 0; j < CPH; j++){
        acc[j][0]=0ull; acc[j][1]=0ull; acc[j][2]=0ull; acc[j][3]=0ull;
    }

    #pragma unroll
    for (int c = 0; c < 6; c++){
        cpa_wait_n(5 - c);
        __syncthreads();

        const float* xb = &xs[c][0];
        #pragma unroll
        for (int icl = 0; icl < 8; icl++){
            const float4* xp = reinterpret_cast<const float4*>(xb + icl*256 + pxq*8);
            float4 xa = xp[0];
            float4 xc = xp[1];
            unsigned long long a01 = pk2(xa.x, xa.y), a23 = pk2(xa.z, xa.w);
            unsigned long long b01 = pk2(xc.x, xc.y), b23 = pk2(xc.z, xc.w);
            #pragma unroll
            for (int j = 0; j < CPH; j++){
                unsigned long long w = ws[(ocg*CPH + j)*DIM + c*8 + icl];
                fma2(acc[j][0], a01, w);
                fma2(acc[j][1], a23, w);
                fma2(acc[j][2], b01, w);
                fma2(acc[j][3], b23, w);
            }
        }
    }

    float* op = out + (size_t)b*outBC*NPIX + base + pxq*8;
    #pragma unroll
    for (int j = 0; j < CPH; j++){
        float* o = op + (size_t)(zh*DIM + ocg*CPH + j)*NPIX;
        float2 l0 = unpk(acc[j][0]), h0 = unpk(acc[j][1]);
        float2 l1 = unpk(acc[j][2]), h1 = unpk(acc[j][3]);
        *reinterpret_cast<float4*>(o)     = make_float4(l0.x, l0.y, h0.x, h0.y);
        *reinterpret_cast<float4*>(o + 4) = make_float4(l1.x, l1.y, h1.x, h1.y);
    }
}

// q,k depthwise 3x3 + Gram/norm. One (b,h) per block; block covers 32x128 px.
// (unchanged from round 5/6 — protected)
__global__ __launch_bounds__(256, 2) void qk_gram_kernel(const float* __restrict__ Wq2,
                                                         const float* __restrict__ Wkv2){
    __shared__ float wq[CPH*9], wk[CPH*9];
    __shared__ float accs[48];
    const int tid = threadIdx.x;
    const int bh  = blockIdx.z;
    const int b   = bh >> 3, h = bh & 7;
    if (tid < CPH*9){
        int c6 = tid/9, t = tid%9;
        wq[tid] = Wq2[(h*CPH + c6)*27 + 9 + t];
    } else if (tid >= 64 && tid < 64 + CPH*9){
        int e = tid - 64, c6 = e/9, t = e%9;
        wk[e] = Wkv2[(h*CPH + c6)*27 + 9 + t];
    } else if (tid >= 128 && tid < 176){
        accs[tid - 128] = 0.f;
    }
    __syncthreads();

    const int lane = tid & 31;
    const int w    = tid >> 5;
    const int x0   = blockIdx.x*32;
    const int x    = x0 + lane;
    const bool xm = (x > 0), xp = (x < WW-1);
    const bool xfast = (x0 > 0) && (x0 + 32 < WW);

    const float* qbase = g_pwq  + (size_t)b*DIM*NPIX   + (size_t)h*CPH*NPIX;
    const float* kbase = g_pwkv + (size_t)b*2*DIM*NPIX + (size_t)h*CPH*NPIX;

    float G[36], qn[CPH], kn[CPH];
    #pragma unroll
    for (int i = 0; i < 36; i++) G[i] = 0.f;
    #pragma unroll
    for (int i = 0; i < CPH; i++){ qn[i] = 0.f; kn[i] = 0.f; }

    #pragma unroll 1
    for (int t4 = 0; t4 < 4; t4++){
        const int y0   = blockIdx.y*128 + t4*32 + w*4;
        const int ytop = y0 - 1;
        const bool fast = xfast && (ytop >= 0) && (ytop + 5 < HH);

        float ka[CPH][4];
        #pragma unroll
        for (int c6 = 0; c6 < CPH; c6++){
            float o[4];
            winconv<6>(kbase + (size_t)c6*NPIX, x, xm, xp, ytop, fast, &wk[c6*9], o);
            #pragma unroll
            for (int i = 0; i < 4; i++){ ka[c6][i] = o[i]; kn[c6] += o[i]*o[i]; }
        }
        #pragma unroll
        for (int c6 = 0; c6 < CPH; c6++){
            float o[4];
            winconv<6>(qbase + (size_t)c6*NPIX, x, xm, xp, ytop, fast, &wq[c6*9], o);
            #pragma unroll
            for (int i = 0; i < 4; i++) qn[c6] += o[i]*o[i];
            #pragma unroll
            for (int d6 = 0; d6 < CPH; d6++)
                G[c6*CPH + d6] += o[0]*ka[d6][0] + o[1]*ka[d6][1]
                                + o[2]*ka[d6][2] + o[3]*ka[d6][3];
        }
    }

    #pragma unroll
    for (int j = 0; j < 36; j++){
        float v = G[j];
        #pragma unroll
        for (int o = 16; o; o >>= 1) v += __shfl_xor_sync(0xffffffffu, v, o);
        if (lane == 0) atomicAdd(&accs[j], v);
    }
    #pragma unroll
    for (int j = 0; j < CPH; j++){
        float v = qn[j];
        #pragma unroll
        for (int o = 16; o; o >>= 1) v += __shfl_xor_sync(0xffffffffu, v, o);
        if (lane == 0) atomicAdd(&accs[36 + j], v);
        float u = kn[j];
        #pragma unroll
        for (int o = 16; o; o >>= 1) u += __shfl_xor_sync(0xffffffffu, u, o);
        if (lane == 0) atomicAdd(&accs[42 + j], u);
    }
    __syncthreads();
    if (tid < 48) atomicAdd(&g_acc[(b*HEADS + h)*48 + tid], accs[tid]);
}

// softmax + fold Wout -> Meff[b] (48x48)
__global__ void attn_kernel(const float* __restrict__ Wout,
                            const float* __restrict__ temp){
    __shared__ float attn_s[BATCH*HEADS*36];
    int t = threadIdx.x;
    if (t < BATCH*HEADS*CPH){
        int b  = t/(HEADS*CPH);
        int h  = (t/CPH)%HEADS;
        int c6 = t%CPH;
        const float* a = g_acc + (b*HEADS + h)*48;
        float qnorm = fmaxf(sqrtf(a[36 + c6]), 1e-12f);
        float s[CPH];
        float mx = -1e30f;
        #pragma unroll
        for (int d6 = 0; d6 < CPH; d6++){
            float knorm = fmaxf(sqrtf(a[42 + d6]), 1e-12f);
            float v = a[c6*CPH + d6] / (qnorm*knorm) * temp[h];
            s[d6] = v; mx = fmaxf(mx, v);
        }
        float sum = 0.f;
        #pragma unroll
        for (int d6 = 0; d6 < CPH; d6++){ s[d6] = expf(s[d6]-mx); sum += s[d6]; }
        float inv = 1.f/sum;
        #pragma unroll
        for (int d6 = 0; d6 < CPH; d6++)
            attn_s[(b*HEADS + h)*36 + c6*CPH + d6] = s[d6]*inv;
    }
    __syncthreads();
    for (int e = t; e < BATCH*DIM*DIM; e += blockDim.x){
        int b = e/(DIM*DIM), rem = e%(DIM*DIM), o = rem/DIM, d = rem%DIM;
        int h = d/CPH, d6 = d%CPH;
        float s = 0.f;
        #pragma unroll
        for (int c6 = 0; c6 < CPH; c6++)
            s += Wout[o*DIM + h*CPH + c6] * attn_s[(b*HEADS + h)*36 + c6*CPH + d6];
        g_meff[e] = s;
    }
}

// depthwise 3x3 for v channels -> g_v
__global__ __launch_bounds__(256, 2) void v_conv_kernel(const float* __restrict__ Wkv2){
    __shared__ float wv[DIM*9];
    const int tid = threadIdx.x;
    for (int t = tid; t < DIM*9; t += 256)
        wv[t] = Wkv2[(DIM + t/9)*27 + 9 + (t%9)];
    __syncthreads();

    const int lane = tid & 31;
    const int w    = tid >> 5;
    const int b    = blockIdx.z;
    const int x0   = blockIdx.x*32;
    const int x    = x0 + lane;
    const int yb   = blockIdx.y*8;
    const bool xm = (x > 0), xp = (x < WW-1);
    const bool fast = (x0 > 0) && (x0 + 32 < WW) && (yb > 0) && (yb + 9 < HH);

    const float* vbase = g_pwkv + (size_t)b*2*DIM*NPIX + (size_t)DIM*NPIX;
    float* vo = g_v + (size_t)b*DIM*NPIX;
    #pragma unroll
    for (int c6 = 0; c6 < CPH; c6++){
        int c = w*CPH + c6;
        float o[8];
        winconv<10>(vbase + (size_t)c*NPIX, x, xm, xp, yb - 1, fast, &wv[c*9], o);
        #pragma unroll
        for (int i = 0; i < 8; i++)
            vo[(size_t)c*NPIX + (size_t)(yb + i)*WW + x] = o[i];
    }
}

// ---------------- launch ----------------
extern "C" void kernel_launch(void* const* d_in, const int* in_sizes, int n_in,
                              void* d_out, int out_size){
    const float* img  = (const float*)d_in[0];
    const float* evs  = (const float*)d_in[1];
    const float* Wq1  = (const float*)d_in[2];
    const float* Wq2  = (const float*)d_in[3];
    const float* Wkv1 = (const float*)d_in[4];
    const float* Wkv2 = (const float*)d_in[5];
    const float* Wout = (const float*)d_in[6];
    const float* temp = (const float*)d_in[7];
    float* out = (float*)d_out;

    float *pwq, *pwkv, *vbuf, *meff;
    cudaGetSymbolAddress((void**)&pwq,  g_pwq);
    cudaGetSymbolAddress((void**)&pwkv, g_pwkv);
    cudaGetSymbolAddress((void**)&vbuf, g_v);
    cudaGetSymbolAddress((void**)&meff, g_meff);

    static cudaStream_t s2 = nullptr;
    static cudaEvent_t  evF = nullptr, evK = nullptr, evV = nullptr;
    if (s2 == nullptr){
        cudaStreamCreateWithFlags(&s2, cudaStreamNonBlocking);
        cudaEventCreateWithFlags(&evF, cudaEventDisableTiming);
        cudaEventCreateWithFlags(&evK, cudaEventDisableTiming);
        cudaEventCreateWithFlags(&evV, cudaEventDisableTiming);
    }

    zero_acc_kernel<<<3, 256>>>();

    cudaEventRecord(evF, 0);
    cudaStreamWaitEvent(s2, evF, 0);

    dim3 gpw(NPIX/256, BATCH, 1);
    // stream B: k-half of img pw, then v-half + v depthwise conv
    pw_cp_kernel<<<gpw, 256, 0, s2>>>(img, Wkv1, pwkv, DIM, 2*DIM, 0, 0);
    cudaEventRecord(evK, s2);
    pw_cp_kernel<<<gpw, 256, 0, s2>>>(img, Wkv1, pwkv, DIM, 2*DIM, 1, 0);
    dim3 gvc(WW/32, HH/8, BATCH);
    v_conv_kernel<<<gvc, 256, 0, s2>>>(Wkv2);
    cudaEventRecord(evV, s2);

    // main: evs pw, then qk (needs k-half), attn, final GEMM (needs g_v)
    pw_cp_kernel<<<gpw, 256>>>(evs, Wq1, pwq, DIM, DIM, 0, 0);
    cudaStreamWaitEvent(0, evK, 0);

    dim3 gqk(WW/32, HH/128, BATCH*HEADS);
    qk_gram_kernel<<<gqk, 256>>>(Wq2, Wkv2);

    attn_kernel<<<1, 256>>>(Wout, temp);

    cudaStreamWaitEvent(0, evV, 0);
    pw_cp_kernel<<<gpw, 256>>>(vbuf, meff, out, DIM, DIM, 0, DIM*DIM);
}

// round 10
// speedup vs baseline: 1.7990x; 1.5652x over previous
#include <cuda_runtime.h>
#include <math.h>

#define BATCH 2
#define DIM   48
#define HEADS 8
#define CPH   6
#define HH    384
#define WW    384
#define NPIX  (HH*WW)

#define PXB 384          // pixels per pw block
#define PXS 392          // padded smem stride (floats); 392%32=8 -> conflict-free B loads

// ---------------- scratch ----------------
__device__ float g_pwq [BATCH*DIM*NPIX];      // 56.6 MB
__device__ float g_pwkv[BATCH*2*DIM*NPIX];    // 113 MB (k: ch 0..47, v: ch 48..95)
__device__ float g_v   [BATCH*DIM*NPIX];      // 56.6 MB
__device__ float g_acc [BATCH*HEADS*48];      // 36 Gram + 6 |q|^2 + 6 |k|^2
__device__ float g_meff[BATCH*DIM*DIM];

// ---------------- helpers ----------------
__device__ __forceinline__ void cpa16(unsigned int dst, const float* src){
    asm volatile("cp.async.cg.shared.global [%0], [%1], 16;" :: "r"(dst), "l"(src) : "memory");
}
__device__ __forceinline__ void cpa_commit(){
    asm volatile("cp.async.commit_group;" ::: "memory");
}
template<int N>
__device__ __forceinline__ void cpa_wait(){
    asm volatile("cp.async.wait_group %0;" :: "n"(N) : "memory");
}
__device__ __forceinline__ unsigned int f2tf32(float x){
    unsigned int u;
    asm("cvt.rna.tf32.f32 %0, %1;" : "=r"(u) : "f"(x));
    return u;
}
__device__ __forceinline__ void mma_tf32(float* d,
                                         const unsigned int* a,
                                         unsigned int b0, unsigned int b1){
    asm volatile(
        "mma.sync.aligned.m16n8k8.row.col.f32.tf32.tf32.f32 "
        "{%0,%1,%2,%3}, {%4,%5,%6,%7}, {%8,%9}, {%0,%1,%2,%3};"
        : "+f"(d[0]), "+f"(d[1]), "+f"(d[2]), "+f"(d[3])
        : "r"(a[0]), "r"(a[1]), "r"(a[2]), "r"(a[3]), "r"(b0), "r"(b1));
}

// Upfront-window depthwise conv (global-memory version)
template<int R>
__device__ __forceinline__ void winconv(const float* __restrict__ chan, int x,
                                        bool xm, bool xp, int ytop, bool fast,
                                        const float* __restrict__ wr, float* out){
    float v[R][3];
    if (fast){
        const float* rp = chan + (size_t)ytop*WW + x;
        #pragma unroll
        for (int r = 0; r < R; r++){
            v[r][0] = __ldg(rp + r*WW - 1);
            v[r][1] = __ldg(rp + r*WW    );
            v[r][2] = __ldg(rp + r*WW + 1);
        }
    } else {
        int xl = max(x-1, 0), xr = min(x+1, WW-1);
        #pragma unroll
        for (int r = 0; r < R; r++){
            int yy = ytop + r; bool yok = (yy >= 0 && yy < HH);
            const float* rp = chan + (size_t)(yok ? yy : 0)*WW;
            v[r][0] = (yok && xm) ? __ldg(rp + xl) : 0.f;
            v[r][1] =  yok        ? __ldg(rp + x ) : 0.f;
            v[r][2] = (yok && xp) ? __ldg(rp + xr) : 0.f;
        }
    }
    #pragma unroll
    for (int i = 0; i < R-2; i++){
        out[i] = wr[0]*v[i  ][0] + wr[1]*v[i  ][1] + wr[2]*v[i  ][2]
               + wr[3]*v[i+1][0] + wr[4]*v[i+1][1] + wr[5]*v[i+1][2]
               + wr[6]*v[i+2][0] + wr[7]*v[i+2][1] + wr[8]*v[i+2][2];
    }
}

// ---------------- kernels ----------------
__global__ void zero_acc_kernel(){
    int t = blockIdx.x*blockDim.x + threadIdx.x;
    if (t < BATCH*HEADS*48) g_acc[t] = 0.f;
}

// 1x1 conv as tf32 tensor-core GEMM.
// Block: 384 threads = 12 warps = 3 m-tiles (16 oc) x 4 n-groups (96 px each).
// X staged via cp.async into padded smem; W cached as tf32 A-fragments in regs.
__global__ __launch_bounds__(384, 2) void pw_mma_kernel(const float* __restrict__ in,
                                                        const float* __restrict__ W,
                                                        float* __restrict__ out,
                                                        int inBC, int outBC,
                                                        int zbase, int wStride){
    extern __shared__ float dsm[];
    float* xs = dsm;                                           // 48 x PXS floats
    unsigned int* wsm = (unsigned int*)(dsm + 48*PXS);         // 48 x 49 tf32 bits

    const int tid = threadIdx.x;
    const int b   = blockIdx.y;
    const int zh  = blockIdx.z + zbase;
    const float* Wb = W + b*wStride + zh*DIM*DIM;

    // stage X (one shot, 12 cp.async per thread)
    const int base = blockIdx.x*PXB;
    const float* inp = in + (size_t)b*inBC*NPIX + base;
    const unsigned int xsu = (unsigned int)__cvta_generic_to_shared(xs);
    #pragma unroll
    for (int r = 0; r < 12; r++){
        int e  = tid + r*384;
        int ic = e/96, q = e%96;
        cpa16(xsu + (unsigned int)((ic*PXS + q*4)*4),
              inp + (size_t)ic*NPIX + q*4);
    }
    cpa_commit();

    // weights -> tf32 smem while copies fly
    #pragma unroll
    for (int r = 0; r < 6; r++){
        int t = tid + r*384;
        int oc = t/48, ic = t%48;
        wsm[oc*49 + ic] = f2tf32(Wb[t]);
    }

    cpa_wait<0>();
    __syncthreads();

    const int w    = tid >> 5;
    const int lane = tid & 31;
    const int mt   = w % 3;        // m-tile (16 oc)
    const int ng   = w / 3;        // n-group (12 n-tiles of 8 px)
    const int gid  = lane >> 2;    // 0..7
    const int tig  = lane & 3;     // 0..3

    // persistent A fragments: 6 k-steps x 4 regs
    unsigned int a[6][4];
    #pragma unroll
    for (int ks = 0; ks < 6; ks++){
        int r0 = mt*16 + gid, k0 = ks*8 + tig;
        a[ks][0] = wsm[ r0     *49 + k0    ];
        a[ks][1] = wsm[(r0 + 8)*49 + k0    ];
        a[ks][2] = wsm[ r0     *49 + k0 + 4];
        a[ks][3] = wsm[(r0 + 8)*49 + k0 + 4];
    }

    float* op = out + (size_t)b*outBC*NPIX + (size_t)zh*DIM*NPIX + base;
    const int r0 = mt*16 + gid;

    #pragma unroll
    for (int i = 0; i < 12; i++){
        const int px0 = (ng*12 + i)*8;
        float d[4] = {0.f, 0.f, 0.f, 0.f};
        #pragma unroll
        for (int ks = 0; ks < 6; ks++){
            unsigned int b0 = f2tf32(xs[(ks*8 + tig    )*PXS + px0 + gid]);
            unsigned int b1 = f2tf32(xs[(ks*8 + tig + 4)*PXS + px0 + gid]);
            mma_tf32(d, a[ks], b0, b1);
        }
        *reinterpret_cast<float2*>(op + (size_t)r0*NPIX     + px0 + tig*2) = make_float2(d[0], d[1]);
        *reinterpret_cast<float2*>(op + (size_t)(r0+8)*NPIX + px0 + tig*2) = make_float2(d[2], d[3]);
    }
}

// q,k depthwise 3x3 + Gram/norm. One (b,h) per block; block covers 32x128 px. (protected)
__global__ __launch_bounds__(256, 2) void qk_gram_kernel(const float* __restrict__ Wq2,
                                                         const float* __restrict__ Wkv2){
    __shared__ float wq[CPH*9], wk[CPH*9];
    __shared__ float accs[48];
    const int tid = threadIdx.x;
    const int bh  = blockIdx.z;
    const int b   = bh >> 3, h = bh & 7;
    if (tid < CPH*9){
        int c6 = tid/9, t = tid%9;
        wq[tid] = Wq2[(h*CPH + c6)*27 + 9 + t];
    } else if (tid >= 64 && tid < 64 + CPH*9){
        int e = tid - 64, c6 = e/9, t = e%9;
        wk[e] = Wkv2[(h*CPH + c6)*27 + 9 + t];
    } else if (tid >= 128 && tid < 176){
        accs[tid - 128] = 0.f;
    }
    __syncthreads();

    const int lane = tid & 31;
    const int w    = tid >> 5;
    const int x0   = blockIdx.x*32;
    const int x    = x0 + lane;
    const bool xm = (x > 0), xp = (x < WW-1);
    const bool xfast = (x0 > 0) && (x0 + 32 < WW);

    const float* qbase = g_pwq  + (size_t)b*DIM*NPIX   + (size_t)h*CPH*NPIX;
    const float* kbase = g_pwkv + (size_t)b*2*DIM*NPIX + (size_t)h*CPH*NPIX;

    float G[36], qn[CPH], kn[CPH];
    #pragma unroll
    for (int i = 0; i < 36; i++) G[i] = 0.f;
    #pragma unroll
    for (int i = 0; i < CPH; i++){ qn[i] = 0.f; kn[i] = 0.f; }

    #pragma unroll 1
    for (int t4 = 0; t4 < 4; t4++){
        const int y0   = blockIdx.y*128 + t4*32 + w*4;
        const int ytop = y0 - 1;
        const bool fast = xfast && (ytop >= 0) && (ytop + 5 < HH);

        float ka[CPH][4];
        #pragma unroll
        for (int c6 = 0; c6 < CPH; c6++){
            float o[4];
            winconv<6>(kbase + (size_t)c6*NPIX, x, xm, xp, ytop, fast, &wk[c6*9], o);
            #pragma unroll
            for (int i = 0; i < 4; i++){ ka[c6][i] = o[i]; kn[c6] += o[i]*o[i]; }
        }
        #pragma unroll
        for (int c6 = 0; c6 < CPH; c6++){
            float o[4];
            winconv<6>(qbase + (size_t)c6*NPIX, x, xm, xp, ytop, fast, &wq[c6*9], o);
            #pragma unroll
            for (int i = 0; i < 4; i++) qn[c6] += o[i]*o[i];
            #pragma unroll
            for (int d6 = 0; d6 < CPH; d6++)
                G[c6*CPH + d6] += o[0]*ka[d6][0] + o[1]*ka[d6][1]
                                + o[2]*ka[d6][2] + o[3]*ka[d6][3];
        }
    }

    #pragma unroll
    for (int j = 0; j < 36; j++){
        float v = G[j];
        #pragma unroll
        for (int o = 16; o; o >>= 1) v += __shfl_xor_sync(0xffffffffu, v, o);
        if (lane == 0) atomicAdd(&accs[j], v);
    }
    #pragma unroll
    for (int j = 0; j < CPH; j++){
        float v = qn[j];
        #pragma unroll
        for (int o = 16; o; o >>= 1) v += __shfl_xor_sync(0xffffffffu, v, o);
        if (lane == 0) atomicAdd(&accs[36 + j], v);
        float u = kn[j];
        #pragma unroll
        for (int o = 16; o; o >>= 1) u += __shfl_xor_sync(0xffffffffu, u, o);
        if (lane == 0) atomicAdd(&accs[42 + j], u);
    }
    __syncthreads();
    if (tid < 48) atomicAdd(&g_acc[(b*HEADS + h)*48 + tid], accs[tid]);
}

// softmax + fold Wout -> Meff[b] (48x48)
__global__ void attn_kernel(const float* __restrict__ Wout,
                            const float* __restrict__ temp){
    __shared__ float attn_s[BATCH*HEADS*36];
    int t = threadIdx.x;
    if (t < BATCH*HEADS*CPH){
        int b  = t/(HEADS*CPH);
        int h  = (t/CPH)%HEADS;
        int c6 = t%CPH;
        const float* a = g_acc + (b*HEADS + h)*48;
        float qnorm = fmaxf(sqrtf(a[36 + c6]), 1e-12f);
        float s[CPH];
        float mx = -1e30f;
        #pragma unroll
        for (int d6 = 0; d6 < CPH; d6++){
            float knorm = fmaxf(sqrtf(a[42 + d6]), 1e-12f);
            float v = a[c6*CPH + d6] / (qnorm*knorm) * temp[h];
            s[d6] = v; mx = fmaxf(mx, v);
        }
        float sum = 0.f;
        #pragma unroll
        for (int d6 = 0; d6 < CPH; d6++){ s[d6] = expf(s[d6]-mx); sum += s[d6]; }
        float inv = 1.f/sum;
        #pragma unroll
        for (int d6 = 0; d6 < CPH; d6++)
            attn_s[(b*HEADS + h)*36 + c6*CPH + d6] = s[d6]*inv;
    }
    __syncthreads();
    for (int e = t; e < BATCH*DIM*DIM; e += blockDim.x){
        int b = e/(DIM*DIM), rem = e%(DIM*DIM), o = rem/DIM, d = rem%DIM;
        int h = d/CPH, d6 = d%CPH;
        float s = 0.f;
        #pragma unroll
        for (int c6 = 0; c6 < CPH; c6++)
            s += Wout[o*DIM + h*CPH + c6] * attn_s[(b*HEADS + h)*36 + c6*CPH + d6];
        g_meff[e] = s;
    }
}

// depthwise 3x3 for v channels -> g_v
__global__ __launch_bounds__(256, 2) void v_conv_kernel(const float* __restrict__ Wkv2){
    __shared__ float wv[DIM*9];
    const int tid = threadIdx.x;
    for (int t = tid; t < DIM*9; t += 256)
        wv[t] = Wkv2[(DIM + t/9)*27 + 9 + (t%9)];
    __syncthreads();

    const int lane = tid & 31;
    const int w    = tid >> 5;
    const int b    = blockIdx.z;
    const int x0   = blockIdx.x*32;
    const int x    = x0 + lane;
    const int yb   = blockIdx.y*8;
    const bool xm = (x > 0), xp = (x < WW-1);
    const bool fast = (x0 > 0) && (x0 + 32 < WW) && (yb > 0) && (yb + 9 < HH);

    const float* vbase = g_pwkv + (size_t)b*2*DIM*NPIX + (size_t)DIM*NPIX;
    float* vo = g_v + (size_t)b*DIM*NPIX;
    #pragma unroll
    for (int c6 = 0; c6 < CPH; c6++){
        int c = w*CPH + c6;
        float o[8];
        winconv<10>(vbase + (size_t)c*NPIX, x, xm, xp, yb - 1, fast, &wv[c*9], o);
        #pragma unroll
        for (int i = 0; i < 8; i++)
            vo[(size_t)c*NPIX + (size_t)(yb + i)*WW + x] = o[i];
    }
}

// ---------------- launch ----------------
extern "C" void kernel_launch(void* const* d_in, const int* in_sizes, int n_in,
                              void* d_out, int out_size){
    const float* img  = (const float*)d_in[0];
    const float* evs  = (const float*)d_in[1];
    const float* Wq1  = (const float*)d_in[2];
    const float* Wq2  = (const float*)d_in[3];
    const float* Wkv1 = (const float*)d_in[4];
    const float* Wkv2 = (const float*)d_in[5];
    const float* Wout = (const float*)d_in[6];
    const float* temp = (const float*)d_in[7];
    float* out = (float*)d_out;

    float *pwq, *pwkv, *vbuf, *meff;
    cudaGetSymbolAddress((void**)&pwq,  g_pwq);
    cudaGetSymbolAddress((void**)&pwkv, g_pwkv);
    cudaGetSymbolAddress((void**)&vbuf, g_v);
    cudaGetSymbolAddress((void**)&meff, g_meff);

    static cudaStream_t s2 = nullptr;
    static cudaEvent_t  evF = nullptr, evK = nullptr, evV = nullptr;
    if (s2 == nullptr){
        cudaStreamCreateWithFlags(&s2, cudaStreamNonBlocking);
        cudaEventCreateWithFlags(&evF, cudaEventDisableTiming);
        cudaEventCreateWithFlags(&evK, cudaEventDisableTiming);
        cudaEventCreateWithFlags(&evV, cudaEventDisableTiming);
    }

    const int smem_pw = (48*PXS + 48*49)*4;  // 84,672 B
    cudaFuncSetAttribute(pw_mma_kernel, cudaFuncAttributeMaxDynamicSharedMemorySize, smem_pw);

    zero_acc_kernel<<<3, 256>>>();

    cudaEventRecord(evF, 0);
    cudaStreamWaitEvent(s2, evF, 0);

    dim3 gpw(NPIX/PXB, BATCH, 1);
    // stream B: k-half of img pw, then v-half + v depthwise conv
    pw_mma_kernel<<<gpw, 384, smem_pw, s2>>>(img, Wkv1, pwkv, DIM, 2*DIM, 0, 0);
    cudaEventRecord(evK, s2);
    pw_mma_kernel<<<gpw, 384, smem_pw, s2>>>(img, Wkv1, pwkv, DIM, 2*DIM, 1, 0);
    dim3 gvc(WW/32, HH/8, BATCH);
    v_conv_kernel<<<gvc, 256, 0, s2>>>(Wkv2);
    cudaEventRecord(evV, s2);

    // main: evs pw, then qk (needs k-half), attn, final GEMM (needs g_v)
    pw_mma_kernel<<<gpw, 384, smem_pw>>>(evs, Wq1, pwq, DIM, DIM, 0, 0);
    cudaStreamWaitEvent(0, evK, 0);

    dim3 gqk(WW/32, HH/128, BATCH*HEADS);
    qk_gram_kernel<<<gqk, 256>>>(Wq2, Wkv2);

    attn_kernel<<<1, 256>>>(Wout, temp);

    cudaStreamWaitEvent(0, evV, 0);
    pw_mma_kernel<<<gpw, 384, smem_pw>>>(vbuf, meff, out, DIM, DIM, 0, DIM*DIM);
}